// round 2
// baseline (speedup 1.0000x reference)
#include <cuda_runtime.h>
#include <cstdint>

// Problem constants
#define BS      2
#define C_IN    64
#define NP      1024
#define NA      60
#define NA_OUT  60
#define KS      3
#define ANN     8
#define C_OUT   128
#define K_DIM   (C_IN * KS)        // 192
#define NPAIRS  (NA_OUT * KS)      // 180

#define NTHREADS 256

// smem layout (floats)
#define WPAD   132                  // W row stride (mult of 4, low-conflict transpose write)
#define VPAD   68                   // v row stride (mult of 4 -> 16B-aligned rows)
#define FPAD   61                   // feats row stride (odd -> conflict-free gather)

#define SMEM_W_FLOATS  (K_DIM * WPAD)            // 25344
#define SMEM_V_FLOATS  (K_DIM * VPAD)            // 13056
#define SMEM_F_FLOATS  (C_IN * FPAD)             // 3904
#define SMEM_V_OFF     (SMEM_W_FLOATS)
#define SMEM_F_OFF     (SMEM_W_FLOATS + SMEM_V_FLOATS)
#define SMEM_FLOATS    (SMEM_W_FLOATS + SMEM_V_FLOATS + SMEM_F_FLOATS)  // 42304
#define SMEM_BYTES     (SMEM_FLOATS * 4)         // 169216

// ---- packed f32x2 helpers carried in uint64 ("l" constraint needs integer 64-bit) ----
typedef unsigned long long u64;

__device__ __forceinline__ u64 pack2(float lo, float hi) {
    u64 d;
    asm("mov.b64 %0, {%1, %2};" : "=l"(d) : "f"(lo), "f"(hi));
    return d;
}
__device__ __forceinline__ void unpack2(float& lo, float& hi, u64 v) {
    asm("mov.b64 {%0, %1}, %2;" : "=f"(lo), "=f"(hi) : "l"(v));
}
__device__ __forceinline__ void fma2(u64& acc, u64 a, u64 b) {
    asm("fma.rn.f32x2 %0, %1, %2, %0;" : "+l"(acc) : "l"(a), "l"(b));
}

__global__ __launch_bounds__(NTHREADS, 1)
void intrazp_fused_kernel(const float* __restrict__ feats,
                          const float* __restrict__ intra_w,
                          const float* __restrict__ Wmat,
                          const float* __restrict__ bias,
                          const int*   __restrict__ intra_idx,
                          float* __restrict__ out)
{
    extern __shared__ float smem[];
    float* Wsm = smem;                 // [k][od], stride WPAD
    float* Vsm = smem + SMEM_V_OFF;    // [k_idx][o], stride VPAD
    float* Fsm = smem + SMEM_F_OFF;    // [c][a],   stride FPAD

    const int p   = blockIdx.x;        // point index
    const int b   = blockIdx.y;        // batch
    const int tid = threadIdx.x;

    // ---- load W transposed: Wsm[k*WPAD + od] = W[od*192 + k] (coalesced gmem reads) ----
    #pragma unroll
    for (int t = tid; t < C_OUT * K_DIM; t += NTHREADS) {
        int od = t / K_DIM;
        int k  = t - od * K_DIM;
        Wsm[k * WPAD + od] = Wmat[t];
    }

    // ---- load feats slab for this (b, p): 64 rows x 60 floats ----
    for (int t = tid; t < C_IN * NA; t += NTHREADS) {
        int c = t / NA;
        int j = t - c * NA;
        Fsm[c * FPAD + j] =
            feats[(((size_t)b * C_IN + c) * NP + p) * NA + j];
    }
    __syncthreads();

    // ---- Stage A: gather-reduce into v[c*3+k][o] ----
    // One warp owns a (o,k) pair: idx/w loaded once (uniform, broadcast),
    // lanes sweep c (odd FPAD -> conflict-free gather LDS).
    {
        const int warp = tid >> 5;
        const int lane = tid & 31;
        for (int pr = warp; pr < NPAIRS; pr += (NTHREADS / 32)) {
            const int o = pr / KS;
            const int k = pr - o * KS;
            int   iv[ANN];
            float wv[ANN];
            #pragma unroll
            for (int a = 0; a < ANN; a++) {
                iv[a] = intra_idx[pr * ANN + a];
                wv[a] = intra_w[pr * ANN + a];
            }
            #pragma unroll
            for (int half = 0; half < 2; half++) {
                const int c = half * 32 + lane;
                const float* fr = Fsm + c * FPAD;
                float acc = 0.f;
                #pragma unroll
                for (int a = 0; a < ANN; a++) acc = fmaf(fr[iv[a]], wv[a], acc);
                Vsm[(c * KS + k) * VPAD + o] = acc;
            }
        }
    }
    __syncthreads();

    // ---- Stage B: GEMM  out[128 x 60] = W[128 x 192] @ v[192 x 60] + bias ----
    // thread grid 32(m) x 8(n): per-thread tile 4M x 8N, packed f32x2 accumulators.
    const int m0 = (tid & 31) * 4;
    const int n0 = (tid >> 5) * 8;

    u64 acc2[4][4];
    #pragma unroll
    for (int i = 0; i < 4; i++) {
        const float bv = bias[m0 + i];
        const u64 bp = pack2(bv, bv);
        #pragma unroll
        for (int j = 0; j < 4; j++) acc2[i][j] = bp;
    }

    const float* wbase = Wsm + m0;
    const float* vbase = Vsm + n0;
    #pragma unroll 4
    for (int k = 0; k < K_DIM; k++) {
        const float4 wv = *(const float4*)(wbase + k * WPAD);
        const ulonglong2* vr = (const ulonglong2*)(vbase + k * VPAD);
        const u64 v01 = vr[0].x;   // bit-packed (v[n0],   v[n0+1])
        const u64 v23 = vr[0].y;   //            (v[n0+2], v[n0+3])
        const u64 v45 = vr[1].x;
        const u64 v67 = vr[1].y;

        const u64 w0 = pack2(wv.x, wv.x);
        const u64 w1 = pack2(wv.y, wv.y);
        const u64 w2 = pack2(wv.z, wv.z);
        const u64 w3 = pack2(wv.w, wv.w);

        fma2(acc2[0][0], w0, v01); fma2(acc2[0][1], w0, v23);
        fma2(acc2[0][2], w0, v45); fma2(acc2[0][3], w0, v67);
        fma2(acc2[1][0], w1, v01); fma2(acc2[1][1], w1, v23);
        fma2(acc2[1][2], w1, v45); fma2(acc2[1][3], w1, v67);
        fma2(acc2[2][0], w2, v01); fma2(acc2[2][1], w2, v23);
        fma2(acc2[2][2], w2, v45); fma2(acc2[2][3], w2, v67);
        fma2(acc2[3][0], w3, v01); fma2(acc2[3][1], w3, v23);
        fma2(acc2[3][2], w3, v45); fma2(acc2[3][3], w3, v67);
    }

    // ---- epilogue: out[b][m][p][o], o in [n0, n0+8) clipped to NA ----
    #pragma unroll
    for (int i = 0; i < 4; i++) {
        const int m = m0 + i;
        float r[8];
        #pragma unroll
        for (int j = 0; j < 4; j++) unpack2(r[2 * j], r[2 * j + 1], acc2[i][j]);
        float* orow = out + (((size_t)(b * C_OUT + m)) * NP + p) * NA;
        #pragma unroll
        for (int j = 0; j < 8; j++) {
            const int o = n0 + j;
            if (o < NA) orow[o] = r[j];
        }
    }
}

extern "C" void kernel_launch(void* const* d_in, const int* in_sizes, int n_in,
                              void* d_out, int out_size)
{
    const float* feats     = (const float*)d_in[0];  // (2,64,1024,60) f32
    const float* intra_w   = (const float*)d_in[1];  // (60,3,8)       f32
    const float* Wmat      = (const float*)d_in[2];  // (128,192)      f32
    const float* bias      = (const float*)d_in[3];  // (1,128,1)      f32
    const int*   intra_idx = (const int*)  d_in[4];  // (60,3,8)       i32
    float* out = (float*)d_out;                      // (2,128,1024,60) f32

    // 169 KB dynamic smem: raise the opt-in cap (idempotent; not a stream op,
    // graph-capture safe, no allocation).
    cudaFuncSetAttribute(intrazp_fused_kernel,
                         cudaFuncAttributeMaxDynamicSharedMemorySize, SMEM_BYTES);

    dim3 grid(NP, BS);
    intrazp_fused_kernel<<<grid, NTHREADS, SMEM_BYTES>>>(
        feats, intra_w, Wmat, bias, intra_idx, out);
}

// round 3
// speedup vs baseline: 1.4206x; 1.4206x over previous
#include <cuda_runtime.h>
#include <cstdint>

// Problem constants
#define BS      2
#define C_IN    64
#define NP      1024
#define NA      60
#define NA_OUT  60
#define KS      3
#define ANN     8
#define C_OUT   128
#define K_DIM   (C_IN * KS)        // 192
#define NPAIRS  (NA_OUT * KS)      // 180

#define NTHREADS 256

// smem layout (floats) — W no longer staged in smem (global Wt, L1-resident)
#define VPAD   60                   // v row stride (240B rows -> 16B aligned)
#define FPAD   61                   // feats row stride (odd -> conflict-free gather)

#define SMEM_V_FLOATS  (K_DIM * VPAD)            // 11520
#define SMEM_F_FLOATS  (C_IN * FPAD)             // 3904
#define SMEM_F_OFF     (SMEM_V_FLOATS)
#define SMEM_FLOATS    (SMEM_V_FLOATS + SMEM_F_FLOATS)  // 15424
#define SMEM_BYTES     (SMEM_FLOATS * 4)         // 61696  -> 3 CTAs/SM

// Pre-transposed W, shared by all CTAs: Wt[k][od], 192 x 128 floats (96 KB).
__device__ float Wt_g[K_DIM * C_OUT];

// ---- packed f32x2 helpers carried in uint64 ----
typedef unsigned long long u64;

__device__ __forceinline__ u64 pack2(float lo, float hi) {
    u64 d;
    asm("mov.b64 %0, {%1, %2};" : "=l"(d) : "f"(lo), "f"(hi));
    return d;
}
__device__ __forceinline__ void unpack2(float& lo, float& hi, u64 v) {
    asm("mov.b64 {%0, %1}, %2;" : "=f"(lo), "=f"(hi) : "l"(v));
}
__device__ __forceinline__ void fma2(u64& acc, u64 a, u64 b) {
    asm("fma.rn.f32x2 %0, %1, %2, %0;" : "+l"(acc) : "l"(a), "l"(b));
}

// ---- prep: transpose W (128x192 -> 192x128), runs once per launch ----
__global__ void transpose_W_kernel(const float* __restrict__ Wmat) {
    int t = blockIdx.x * 256 + threadIdx.x;
    if (t < C_OUT * K_DIM) {
        int od = t / K_DIM;
        int k  = t - od * K_DIM;
        Wt_g[k * C_OUT + od] = Wmat[t];     // coalesced read, strided write (gmem, fine)
    }
}

__global__ __launch_bounds__(NTHREADS, 3)
void intrazp_fused_kernel(const float* __restrict__ feats,
                          const float* __restrict__ intra_w,
                          const float* __restrict__ bias,
                          const int*   __restrict__ intra_idx,
                          float* __restrict__ out)
{
    extern __shared__ float smem[];
    float* Vsm = smem;                 // [k_idx][o], stride VPAD
    float* Fsm = smem + SMEM_F_OFF;    // [c][a],   stride FPAD

    const int p   = blockIdx.x;        // point index
    const int b   = blockIdx.y;        // batch
    const int tid = threadIdx.x;

    // ---- load feats slab for this (b, p): 64 rows x 60 floats ----
    for (int t = tid; t < C_IN * NA; t += NTHREADS) {
        int c = t / NA;
        int j = t - c * NA;
        Fsm[c * FPAD + j] =
            feats[(((size_t)b * C_IN + c) * NP + p) * NA + j];
    }
    __syncthreads();

    // ---- Stage A: gather-reduce into v[c*3+k][o] ----
    // One warp owns an (o,k) pair: idx/w loaded once (uniform, broadcast),
    // lanes sweep c (odd FPAD -> conflict-free gather LDS).
    {
        const int warp = tid >> 5;
        const int lane = tid & 31;
        for (int pr = warp; pr < NPAIRS; pr += (NTHREADS / 32)) {
            const int o = pr / KS;
            const int k = pr - o * KS;
            int   iv[ANN];
            float wv[ANN];
            #pragma unroll
            for (int a = 0; a < ANN; a++) {
                iv[a] = __ldg(intra_idx + pr * ANN + a);
                wv[a] = __ldg(intra_w  + pr * ANN + a);
            }
            #pragma unroll
            for (int half = 0; half < 2; half++) {
                const int c = half * 32 + lane;
                const float* fr = Fsm + c * FPAD;
                float acc = 0.f;
                #pragma unroll
                for (int a = 0; a < ANN; a++) acc = fmaf(fr[iv[a]], wv[a], acc);
                Vsm[(c * KS + k) * VPAD + o] = acc;
            }
        }
    }
    __syncthreads();

    // ---- Stage B: GEMM  out[128 x 60] = Wt^T[128 x 192] @ v[192 x 60] + bias ----
    // thread grid 32(m) x 8(n): per-thread tile 4M x 8N, packed f32x2 accumulators.
    // W read from global Wt (L1-resident, coalesced 512B/warp); v from smem (broadcast).
    const int m0 = (tid & 31) * 4;
    const int n0 = (tid >> 5) * 8;

    u64 acc2[4][4];
    #pragma unroll
    for (int i = 0; i < 4; i++) {
        const float bv = __ldg(bias + m0 + i);
        const u64 bp = pack2(bv, bv);
        #pragma unroll
        for (int j = 0; j < 4; j++) acc2[i][j] = bp;
    }

    const float4* wq = reinterpret_cast<const float4*>(Wt_g) + (m0 >> 2);
    const float*  vbase = Vsm + n0;
    #pragma unroll 4
    for (int k = 0; k < K_DIM; k++) {
        const float4 wv = __ldg(wq + k * (C_OUT / 4));
        const ulonglong2* vr = (const ulonglong2*)(vbase + k * VPAD);
        const u64 v01 = vr[0].x;   // bit-packed (v[n0],   v[n0+1])
        const u64 v23 = vr[0].y;   //            (v[n0+2], v[n0+3])
        const u64 v45 = vr[1].x;
        const u64 v67 = vr[1].y;

        const u64 w0 = pack2(wv.x, wv.x);
        const u64 w1 = pack2(wv.y, wv.y);
        const u64 w2 = pack2(wv.z, wv.z);
        const u64 w3 = pack2(wv.w, wv.w);

        fma2(acc2[0][0], w0, v01); fma2(acc2[0][1], w0, v23);
        fma2(acc2[0][2], w0, v45); fma2(acc2[0][3], w0, v67);
        fma2(acc2[1][0], w1, v01); fma2(acc2[1][1], w1, v23);
        fma2(acc2[1][2], w1, v45); fma2(acc2[1][3], w1, v67);
        fma2(acc2[2][0], w2, v01); fma2(acc2[2][1], w2, v23);
        fma2(acc2[2][2], w2, v45); fma2(acc2[2][3], w2, v67);
        fma2(acc2[3][0], w3, v01); fma2(acc2[3][1], w3, v23);
        fma2(acc2[3][2], w3, v45); fma2(acc2[3][3], w3, v67);
    }

    // ---- epilogue: out[b][m][p][o], o in [n0, n0+8) clipped to NA ----
    #pragma unroll
    for (int i = 0; i < 4; i++) {
        const int m = m0 + i;
        float r[8];
        #pragma unroll
        for (int j = 0; j < 4; j++) unpack2(r[2 * j], r[2 * j + 1], acc2[i][j]);
        float* orow = out + (((size_t)(b * C_OUT + m)) * NP + p) * NA;
        #pragma unroll
        for (int j = 0; j < 8; j++) {
            const int o = n0 + j;
            if (o < NA) orow[o] = r[j];
        }
    }
}

extern "C" void kernel_launch(void* const* d_in, const int* in_sizes, int n_in,
                              void* d_out, int out_size)
{
    const float* feats     = (const float*)d_in[0];  // (2,64,1024,60) f32
    const float* intra_w   = (const float*)d_in[1];  // (60,3,8)       f32
    const float* Wmat      = (const float*)d_in[2];  // (128,192)      f32
    const float* bias      = (const float*)d_in[3];  // (1,128,1)      f32
    const int*   intra_idx = (const int*)  d_in[4];  // (60,3,8)       i32
    float* out = (float*)d_out;                      // (2,128,1024,60) f32

    cudaFuncSetAttribute(intrazp_fused_kernel,
                         cudaFuncAttributeMaxDynamicSharedMemorySize, SMEM_BYTES);

    // Prep: transpose W into the shared global (same stream -> ordered).
    transpose_W_kernel<<<(C_OUT * K_DIM + 255) / 256, 256>>>(Wmat);

    dim3 grid(NP, BS);
    intrazp_fused_kernel<<<grid, NTHREADS, SMEM_BYTES>>>(
        feats, intra_w, bias, intra_idx, out);
}

// round 5
// speedup vs baseline: 2.5349x; 1.7844x over previous
#include <cuda_runtime.h>
#include <cuda_bf16.h>
#include <cstdint>

// ---------------- problem constants ----------------
#define BS      2
#define C_IN    64
#define NP      1024
#define NA      60
#define KS      3
#define ANN     8
#define C_OUT   128
#define K_DIM   192              // C_IN*KS
#define NPAIRS  180              // NA*KS
#define NJOBS   (BS * NP)        // 2048

#define NTHREADS 256
#define GRID_CTAS 296            // 2 per SM x 148 SMs

#define N_PAD   64               // N padded 60 -> 64
#define KSTEPS  12               // 192 / 16
#define NTILES  8                // 64 / 8

// ---------------- SMEM layout (bytes) ----------------
// B fragment buffers: [ntile 8][kstep 12][lane 32][8B: {k0-7 pair, k8-15 pair}]
#define B_BYTES     (NTILES * KSTEPS * 32 * 8)       // 24576
#define SMEM_BHI    0
#define SMEM_BLO    (SMEM_BHI + B_BYTES)             // 24576
#define FPAD        61
#define SMEM_F      (SMEM_BLO + B_BYTES)             // 49152
#define SMEM_IDX    (SMEM_F + C_IN * FPAD * 4)       // 64768
#define SMEM_WV     (SMEM_IDX + NPAIRS * ANN * 4)    // 70528
#define SMEM_TOTAL  (SMEM_WV + NPAIRS * ANN * 4)     // 76288

// ---------------- A fragments (W), precomputed in HMMA per-lane order ----------------
// [part hi/lo][mtile 8][kstep 12][lane 32][4 x b32]  (16B per lane per tile-step)
__device__ __align__(16) uint32_t Afrag_g[2 * 8 * KSTEPS * 32 * 4];   // 98304 B

__global__ void pack_W_kernel(const float* __restrict__ Wmat) {
    int t = blockIdx.x * 256 + threadIdx.x;          // t = ((part*8+mt)*12+ks)*32+lane
    if (t >= 2 * 8 * KSTEPS * 32) return;
    const int lane = t & 31;
    const int ks   = (t >> 5) % KSTEPS;
    const int mt   = (t >> 5) / KSTEPS % 8;
    const int part = t / (32 * KSTEPS * 8);          // 0 = hi, 1 = lo
    const int r0 = mt * 16 + (lane >> 2);
    const int k0 = ks * 16 + ((lane & 3) << 1);

    uint32_t regs[4];
    #pragma unroll
    for (int reg = 0; reg < 4; reg++) {
        const int r = r0 + ((reg & 1) ? 8 : 0);      // reg0/2: row r0, reg1/3: r0+8
        const int k = k0 + ((reg & 2) ? 8 : 0);      // reg0/1: k0,     reg2/3: k0+8
        float f0 = Wmat[r * K_DIM + k];
        float f1 = Wmat[r * K_DIM + k + 1];
        __nv_bfloat16 h0 = __float2bfloat16_rn(f0);
        __nv_bfloat16 h1 = __float2bfloat16_rn(f1);
        __nv_bfloat16 v0, v1;
        if (part == 0) { v0 = h0; v1 = h1; }
        else {
            v0 = __float2bfloat16_rn(f0 - __bfloat162float(h0));
            v1 = __float2bfloat16_rn(f1 - __bfloat162float(h1));
        }
        regs[reg] = (uint32_t)__bfloat16_as_ushort(v0) |
                    ((uint32_t)__bfloat16_as_ushort(v1) << 16);
    }
    *(uint4*)(Afrag_g + (size_t)t * 4) = make_uint4(regs[0], regs[1], regs[2], regs[3]);
}

// B fragment byte offset for logical element (o = n index, kc = k index):
// lane = ((o&7)<<2) | ((kc>>1)&3);  half = (kc>>3)&1;  byte-in-pair = (kc&1)*2
__device__ __forceinline__ uint32_t bfrag_off(int o, int kc) {
    return (uint32_t)(((((o >> 3) * KSTEPS + (kc >> 4)) * 32 +
                        ((o & 7) << 2) + ((kc >> 1) & 3)) << 3) +
                      (((kc >> 3) & 1) << 2) + ((kc & 1) << 1));
}

__device__ __forceinline__ uint32_t smem_u32(const void* p) {
    uint32_t a;
    asm("{ .reg .u64 t; cvta.to.shared.u64 t, %1; cvt.u32.u64 %0, t; }" : "=r"(a) : "l"(p));
    return a;
}

__device__ __forceinline__ void mma_bf16(float* c, const uint4 a, uint32_t b0, uint32_t b1) {
    asm volatile(
        "mma.sync.aligned.m16n8k16.row.col.f32.bf16.bf16.f32 "
        "{%0,%1,%2,%3}, {%4,%5,%6,%7}, {%8,%9}, {%0,%1,%2,%3};"
        : "+f"(c[0]), "+f"(c[1]), "+f"(c[2]), "+f"(c[3])
        : "r"(a.x), "r"(a.y), "r"(a.z), "r"(a.w), "r"(b0), "r"(b1));
}

// ---------------- main fused kernel (persistent, 2 CTAs/SM) ----------------
__global__ __launch_bounds__(NTHREADS, 2)
void intrazp_mma_kernel(const float* __restrict__ feats,
                        const float* __restrict__ intra_w,
                        const float* __restrict__ bias,
                        const int*   __restrict__ intra_idx,
                        float* __restrict__ out)
{
    extern __shared__ char smem[];
    const uint32_t smb = smem_u32(smem);
    float* Fsm  = (float*)(smem + SMEM_F);
    int*   Ism  = (int*)  (smem + SMEM_IDX);
    float* Wvsm = (float*)(smem + SMEM_WV);
    const int tid = threadIdx.x, wid = tid >> 5, lane = tid & 31;

    // ---- one-time setup: zero B pad rows (o 60..63), cache idx/w in smem ----
    for (int t = tid; t < 4 * K_DIM; t += NTHREADS) {
        const int o = 60 + t / K_DIM, kc = t % K_DIM;
        const uint32_t off = bfrag_off(o, kc);
        asm volatile("st.shared.u16 [%0], %1;" :: "r"(smb + SMEM_BHI + off), "h"((unsigned short)0));
        asm volatile("st.shared.u16 [%0], %1;" :: "r"(smb + SMEM_BLO + off), "h"((unsigned short)0));
    }
    for (int t = tid; t < NPAIRS * ANN; t += NTHREADS) {
        Ism[t]  = __ldg(intra_idx + t);
        Wvsm[t] = __ldg(intra_w + t);
    }

    // per-warp constants for GEMM/epilogue: warp owns rows [wid*16, wid*16+16)
    const int r1 = wid * 16 + (lane >> 2);
    const int r2 = r1 + 8;
    const float bv1 = __ldg(bias + r1);
    const float bv2 = __ldg(bias + r2);
    __syncthreads();

    for (int job = blockIdx.x; job < NJOBS; job += GRID_CTAS) {
        const int b = job >> 10, p = job & (NP - 1);

        // ---- load feats slab (64 x 60) ----
        for (int t = tid; t < C_IN * NA; t += NTHREADS) {
            const int c = t / NA, j = t - c * NA;
            Fsm[c * FPAD + j] = feats[(((size_t)b * C_IN + c) * NP + p) * NA + j];
        }
        __syncthreads();

        // ---- stage A: gather-reduce -> bf16 hi/lo B fragments in smem ----
        for (int pr = wid; pr < NPAIRS; pr += 8) {
            const int o = pr / KS, kk = pr - o * KS;
            int   iv[ANN]; float wv[ANN];
            #pragma unroll
            for (int a = 0; a < ANN; a++) {
                iv[a] = Ism[pr * ANN + a];
                wv[a] = Wvsm[pr * ANN + a];
            }
            #pragma unroll
            for (int half = 0; half < 2; half++) {
                const int c = half * 32 + lane;
                const float* fr = Fsm + c * FPAD;
                float acc = 0.f;
                #pragma unroll
                for (int a = 0; a < ANN; a++) acc = fmaf(fr[iv[a]], wv[a], acc);
                const __nv_bfloat16 h = __float2bfloat16_rn(acc);
                const __nv_bfloat16 l = __float2bfloat16_rn(acc - __bfloat162float(h));
                const uint32_t off = bfrag_off(o, c * KS + kk);
                asm volatile("st.shared.u16 [%0], %1;"
                             :: "r"(smb + SMEM_BHI + off), "h"(__bfloat16_as_ushort(h)));
                asm volatile("st.shared.u16 [%0], %1;"
                             :: "r"(smb + SMEM_BLO + off), "h"(__bfloat16_as_ushort(l)));
            }
        }
        __syncthreads();

        // ---- GEMM: out[128x64] = W @ v, 3-pass split (hi*hi + hi*lo + lo*hi) ----
        float acc[NTILES][4];
        #pragma unroll
        for (int nt = 0; nt < NTILES; nt++) {
            acc[nt][0] = bv1; acc[nt][1] = bv1;
            acc[nt][2] = bv2; acc[nt][3] = bv2;
        }

        #pragma unroll
        for (int pass = 0; pass < 3; pass++) {
            const int apart = (pass == 2) ? 1 : 0;            // A: hi, hi, lo
            const uint32_t bbuf = smb + ((pass == 1) ? SMEM_BLO : SMEM_BHI);
            const uint4* Abase = (const uint4*)Afrag_g +
                                 ((size_t)(apart * 8 + wid) * KSTEPS) * 32;
            #pragma unroll
            for (int ks = 0; ks < KSTEPS; ks++) {
                const uint4 av = __ldg(Abase + ks * 32 + lane);
                #pragma unroll
                for (int nt = 0; nt < NTILES; nt++) {
                    uint32_t b0, b1;
                    asm volatile("ld.shared.v2.b32 {%0,%1}, [%2];"
                                 : "=r"(b0), "=r"(b1)
                                 : "r"(bbuf + (uint32_t)(((nt * KSTEPS + ks) * 32 + lane) * 8)));
                    mma_bf16(acc[nt], av, b0, b1);
                }
            }
        }

        // ---- epilogue: add nothing more (bias pre-seeded), store rows r1/r2 ----
        {
            float* orow1 = out + (((size_t)(b * C_OUT + r1)) * NP + p) * NA;
            float* orow2 = out + (((size_t)(b * C_OUT + r2)) * NP + p) * NA;
            const int ncol = (lane & 3) * 2;
            #pragma unroll
            for (int nt = 0; nt < NTILES; nt++) {
                const int n = nt * 8 + ncol;
                if (n < NA) {
                    *(float2*)(orow1 + n) = make_float2(acc[nt][0], acc[nt][1]);
                    *(float2*)(orow2 + n) = make_float2(acc[nt][2], acc[nt][3]);
                }
            }
        }
        __syncthreads();   // protect Fsm/B buffers before next job
    }
}

extern "C" void kernel_launch(void* const* d_in, const int* in_sizes, int n_in,
                              void* d_out, int out_size)
{
    const float* feats     = (const float*)d_in[0];  // (2,64,1024,60) f32
    const float* intra_w   = (const float*)d_in[1];  // (60,3,8)       f32
    const float* Wmat      = (const float*)d_in[2];  // (128,192)      f32
    const float* bias      = (const float*)d_in[3];  // (1,128,1)      f32
    const int*   intra_idx = (const int*)  d_in[4];  // (60,3,8)       i32
    float* out = (float*)d_out;                      // (2,128,1024,60) f32

    cudaFuncSetAttribute(intrazp_mma_kernel,
                         cudaFuncAttributeMaxDynamicSharedMemorySize, SMEM_TOTAL);

    pack_W_kernel<<<(2 * 8 * KSTEPS * 32 + 255) / 256, 256>>>(Wmat);
    intrazp_mma_kernel<<<GRID_CTAS, NTHREADS, SMEM_TOTAL>>>(
        feats, intra_w, bias, intra_idx, out);
}

// round 6
// speedup vs baseline: 3.5682x; 1.4076x over previous
#include <cuda_runtime.h>
#include <cuda_bf16.h>
#include <cstdint>

// ---------------- problem constants ----------------
#define BS      2
#define C_IN    64
#define NA      60
#define KS      3
#define ANN     8
#define C_OUT   128
#define K_DIM   192              // C_IN*KS
#define NPAIRS  180              // NA*KS
#define NP      1024
#define NJOBS   (BS * NP)        // 2048

#define NTHREADS 256
#define GRID_CTAS 296            // 2 per SM x 148 SMs

#define KSTEPS  12               // 192 / 16
#define NTILES  8                // 64 / 8

// ---------------- SMEM layout (bytes) ----------------
// B fragments, hi/lo interleaved per 16B unit:
//   unit u = (nt*KSTEPS + ks)*32 + lane;  [u*16 .. +8) = hi pair, [+8 .. +16) = lo pair
#define B_BYTES     (NTILES * KSTEPS * 32 * 16)      // 49152
#define SMEM_B      0
#define FPAD        61
#define SMEM_F      B_BYTES                          // 49152
#define SMEM_IDX    (SMEM_F + C_IN * FPAD * 4)       // 64768
#define SMEM_WV     (SMEM_IDX + NPAIRS * ANN * 4)    // 70528
#define SMEM_TOTAL  (SMEM_WV + NPAIRS * ANN * 4)     // 76288

// ---------------- A fragments (W) in HMMA per-lane order ----------------
// [part hi/lo][mtile 8][kstep 12][lane 32][4 x b32]
__device__ __align__(16) uint32_t Afrag_g[2 * 8 * KSTEPS * 32 * 4];   // 98304 B

__global__ void pack_W_kernel(const float* __restrict__ Wmat) {
    int t = blockIdx.x * 256 + threadIdx.x;          // t = ((part*8+mt)*12+ks)*32+lane
    if (t >= 2 * 8 * KSTEPS * 32) return;
    const int lane = t & 31;
    const int ks   = (t >> 5) % KSTEPS;
    const int mt   = (t >> 5) / KSTEPS % 8;
    const int part = t / (32 * KSTEPS * 8);          // 0 = hi, 1 = lo
    const int r0 = mt * 16 + (lane >> 2);
    const int k0 = ks * 16 + ((lane & 3) << 1);

    uint32_t regs[4];
    #pragma unroll
    for (int reg = 0; reg < 4; reg++) {
        const int r = r0 + ((reg & 1) ? 8 : 0);
        const int k = k0 + ((reg & 2) ? 8 : 0);
        float f0 = Wmat[r * K_DIM + k];
        float f1 = Wmat[r * K_DIM + k + 1];
        __nv_bfloat16 h0 = __float2bfloat16_rn(f0);
        __nv_bfloat16 h1 = __float2bfloat16_rn(f1);
        __nv_bfloat16 v0, v1;
        if (part == 0) { v0 = h0; v1 = h1; }
        else {
            v0 = __float2bfloat16_rn(f0 - __bfloat162float(h0));
            v1 = __float2bfloat16_rn(f1 - __bfloat162float(h1));
        }
        regs[reg] = (uint32_t)__bfloat16_as_ushort(v0) |
                    ((uint32_t)__bfloat16_as_ushort(v1) << 16);
    }
    *(uint4*)(Afrag_g + (size_t)t * 4) = make_uint4(regs[0], regs[1], regs[2], regs[3]);
}

// B element byte offset (hi part; lo is +8) for logical (o = n index, kc = k index)
__device__ __forceinline__ uint32_t bfrag_off(int o, int kc) {
    const uint32_t u = (uint32_t)((((o >> 3) * KSTEPS + (kc >> 4)) * 32) +
                                  ((o & 7) << 2) + ((kc >> 1) & 3));
    return (u << 4) + ((((uint32_t)kc >> 3) & 1) << 2) + (((uint32_t)kc & 1) << 1);
}

__device__ __forceinline__ uint32_t smem_u32(const void* p) {
    uint32_t a;
    asm("{ .reg .u64 t; cvta.to.shared.u64 t, %1; cvt.u32.u64 %0, t; }" : "=r"(a) : "l"(p));
    return a;
}

__device__ __forceinline__ void mma_bf16(float* c, const uint4 a, uint32_t b0, uint32_t b1) {
    asm volatile(
        "mma.sync.aligned.m16n8k16.row.col.f32.bf16.bf16.f32 "
        "{%0,%1,%2,%3}, {%4,%5,%6,%7}, {%8,%9}, {%0,%1,%2,%3};"
        : "+f"(c[0]), "+f"(c[1]), "+f"(c[2]), "+f"(c[3])
        : "r"(a.x), "r"(a.y), "r"(a.z), "r"(a.w), "r"(b0), "r"(b1));
}

// ---------------- main fused kernel (persistent, 2 CTAs/SM) ----------------
__global__ __launch_bounds__(NTHREADS, 2)
void intrazp_mma_kernel(const float* __restrict__ feats,
                        const float* __restrict__ intra_w,
                        const float* __restrict__ bias,
                        const int*   __restrict__ intra_idx,
                        float* __restrict__ out)
{
    extern __shared__ char smem[];
    const uint32_t smb = smem_u32(smem);
    float* Fsm  = (float*)(smem + SMEM_F);
    int*   Ism  = (int*)  (smem + SMEM_IDX);
    float* Wvsm = (float*)(smem + SMEM_WV);
    const int tid = threadIdx.x, wid = tid >> 5, lane = tid & 31;

    // warp tiling: 4M x 2N; warp covers rows [32*mq, +32), cols [32*nq, +32)
    const int mq = wid & 3, nq = wid >> 2;

    // ---- one-time: zero B pad rows (o = 60..63), cache idx/w ----
    for (int t = tid; t < 4 * K_DIM; t += NTHREADS) {
        const int o = 60 + t / K_DIM, kc = t % K_DIM;
        const uint32_t off = bfrag_off(o, kc);
        asm volatile("st.shared.u16 [%0], %1;" :: "r"(smb + SMEM_B + off),     "h"((unsigned short)0));
        asm volatile("st.shared.u16 [%0], %1;" :: "r"(smb + SMEM_B + off + 8), "h"((unsigned short)0));
    }
    for (int t = tid; t < NPAIRS * ANN; t += NTHREADS) {
        Ism[t]  = __ldg(intra_idx + t);
        Wvsm[t] = __ldg(intra_w + t);
    }

    // bias for the 4 row-groups this thread accumulates
    const int rb = mq * 32 + (lane >> 2);
    float bv[4];
    #pragma unroll
    for (int i = 0; i < 4; i++) bv[i] = __ldg(bias + rb + i * 8);
    __syncthreads();

    for (int job = blockIdx.x; job < NJOBS; job += GRID_CTAS) {
        const int b = job >> 10, p = job & (NP - 1);

        // ---- load feats slab (64 x 60) as float4 ----
        for (int t = tid; t < C_IN * 15; t += NTHREADS) {
            const int c = t / 15, q = t - c * 15;
            const float4 v = __ldg((const float4*)(feats +
                              (((size_t)b * C_IN + c) * NP + p) * NA) + q);
            float* dst = Fsm + c * FPAD + q * 4;
            dst[0] = v.x; dst[1] = v.y; dst[2] = v.z; dst[3] = v.w;
        }
        __syncthreads();

        // ---- stage A: gather-reduce -> bf16 hi/lo B fragments ----
        for (int pr = wid; pr < NPAIRS; pr += 8) {
            const int o = pr / KS, kk = pr - o * KS;
            int   iv[ANN]; float wv[ANN];
            #pragma unroll
            for (int a = 0; a < ANN; a++) {
                iv[a] = Ism[pr * ANN + a];
                wv[a] = Wvsm[pr * ANN + a];
            }
            #pragma unroll
            for (int half = 0; half < 2; half++) {
                const int c = half * 32 + lane;
                const float* fr = Fsm + c * FPAD;
                float acc = 0.f;
                #pragma unroll
                for (int a = 0; a < ANN; a++) acc = fmaf(fr[iv[a]], wv[a], acc);
                const __nv_bfloat16 h = __float2bfloat16_rn(acc);
                const __nv_bfloat16 l = __float2bfloat16_rn(acc - __bfloat162float(h));
                const uint32_t off = smb + SMEM_B + bfrag_off(o, c * KS + kk);
                asm volatile("st.shared.u16 [%0], %1;" :: "r"(off),     "h"(__bfloat16_as_ushort(h)));
                asm volatile("st.shared.u16 [%0], %1;" :: "r"(off + 8), "h"(__bfloat16_as_ushort(l)));
            }
        }
        __syncthreads();

        // ---- GEMM: fused 3-pass split (hh + hl + lh), warp tile 32M x 32N ----
        float acc[2][4][4];
        #pragma unroll
        for (int mt = 0; mt < 2; mt++)
            #pragma unroll
            for (int j = 0; j < 4; j++) {
                acc[mt][j][0] = bv[2 * mt];     acc[mt][j][1] = bv[2 * mt];
                acc[mt][j][2] = bv[2 * mt + 1]; acc[mt][j][3] = bv[2 * mt + 1];
            }

        const int mt0 = 2 * mq;
        #pragma unroll
        for (int ks = 0; ks < KSTEPS; ks++) {
            // A: hi/lo for both mtiles (L1/L2-resident global fragments)
            uint4 ah[2], al[2];
            #pragma unroll
            for (int mt = 0; mt < 2; mt++) {
                ah[mt] = __ldg((const uint4*)Afrag_g + ((0 * 8 + mt0 + mt) * KSTEPS + ks) * 32 + lane);
                al[mt] = __ldg((const uint4*)Afrag_g + ((1 * 8 + mt0 + mt) * KSTEPS + ks) * 32 + lane);
            }
            // B: hi+lo pairs, one LDS.128 per ntile
            uint32_t bh[4][2], bl[4][2];
            #pragma unroll
            for (int j = 0; j < 4; j++) {
                const int nt = nq * 4 + j;
                asm volatile("ld.shared.v4.b32 {%0,%1,%2,%3}, [%4];"
                             : "=r"(bh[j][0]), "=r"(bh[j][1]), "=r"(bl[j][0]), "=r"(bl[j][1])
                             : "r"(smb + SMEM_B + (uint32_t)(((nt * KSTEPS + ks) * 32 + lane) << 4)));
            }
            #pragma unroll
            for (int j = 0; j < 4; j++) {
                #pragma unroll
                for (int mt = 0; mt < 2; mt++) {
                    mma_bf16(acc[mt][j], ah[mt], bh[j][0], bh[j][1]);   // hi*hi
                    mma_bf16(acc[mt][j], ah[mt], bl[j][0], bl[j][1]);   // hi*lo
                    mma_bf16(acc[mt][j], al[mt], bh[j][0], bh[j][1]);   // lo*hi
                }
            }
        }

        // ---- epilogue: store rows (2 mtiles x 2 row-groups), cols 32*nq..+31 ----
        {
            const int ncol = nq * 32 + (lane & 3) * 2;
            #pragma unroll
            for (int mt = 0; mt < 2; mt++) {
                const int r1 = mq * 32 + mt * 16 + (lane >> 2);
                float* orow1 = out + (((size_t)(b * C_OUT + r1)) * NP + p) * NA;
                float* orow2 = orow1 + (size_t)8 * NP * NA;
                #pragma unroll
                for (int j = 0; j < 4; j++) {
                    const int n = ncol + j * 8;
                    if (n < NA) {
                        *(float2*)(orow1 + n) = make_float2(acc[mt][j][0], acc[mt][j][1]);
                        *(float2*)(orow2 + n) = make_float2(acc[mt][j][2], acc[mt][j][3]);
                    }
                }
            }
        }
        __syncthreads();   // protect Fsm/B before next job
    }
}

extern "C" void kernel_launch(void* const* d_in, const int* in_sizes, int n_in,
                              void* d_out, int out_size)
{
    const float* feats     = (const float*)d_in[0];  // (2,64,1024,60) f32
    const float* intra_w   = (const float*)d_in[1];  // (60,3,8)       f32
    const float* Wmat      = (const float*)d_in[2];  // (128,192)      f32
    const float* bias      = (const float*)d_in[3];  // (1,128,1)      f32
    const int*   intra_idx = (const int*)  d_in[4];  // (60,3,8)       i32
    float* out = (float*)d_out;                      // (2,128,1024,60) f32

    cudaFuncSetAttribute(intrazp_mma_kernel,
                         cudaFuncAttributeMaxDynamicSharedMemorySize, SMEM_TOTAL);

    pack_W_kernel<<<(2 * 8 * KSTEPS * 32 + 255) / 256, 256>>>(Wmat);
    intrazp_mma_kernel<<<GRID_CTAS, NTHREADS, SMEM_TOTAL>>>(
        feats, intra_w, bias, intra_idx, out);
}